// round 12
// baseline (speedup 1.0000x reference)
#include <cuda_runtime.h>
#include <cstdint>

#define GRID    32
#define NCELL   (GRID*GRID*GRID)          // 32768
#define BMAX    4
#define MMAX    4096
#define NMAX    16384
#define DOMAIN  4.5f
#define RMAX    4
#define NCTA    148
#define TPB     256
#define NT      (NCTA*TPB)                // 37888 threads
#define CHUNKC  128                       // cells per chunk
#define NCHUNKT ((BMAX*NCELL)/CHUNKC)     // 1024 chunks
#define CHPB    (NCELL/CHUNKC)            // 256 chunks per batch
#define F_INF   __int_as_float(0x7f800000)

// ---------------- device scratch (allocation-free rule) ----------------
__device__ int      g_cnt[BMAX][NCELL];      // counts -> cursors
__device__ uint32_t g_tbl[BMAX][NCELL];      // start<<16 | cnt
__device__ int      g_ptcell[BMAX][MMAX];
__device__ float4   g_pts[BMAX][MMAX];       // cell-sorted (x,y,z,|p|^2) scaled
__device__ int      g_pidx[BMAX][MMAX];
__device__ int      g_chunksum[NCHUNKT];
__device__ int      g_chunkoff[NCHUNKT];
__device__ int      g_ovf_cnt;
__device__ int      g_ovf[BMAX * NMAX];      // packed b<<20 | n
// software grid barrier state
__device__ int      g_bar_count;
__device__ int      g_bar_gen;

__device__ __forceinline__ void grid_sync() {
    __syncthreads();
    if (threadIdx.x == 0) {
        volatile int* vgen = &g_bar_gen;
        int gen = *vgen;
        __threadfence();
        if (atomicAdd(&g_bar_count, 1) == (int)gridDim.x - 1) {
            g_bar_count = 0;
            __threadfence();
            atomicAdd(&g_bar_gen, 1);
        } else {
            while (*vgen == gen) { __nanosleep(64); }
        }
        __threadfence();
    }
    __syncthreads();
}

__device__ __forceinline__ float decode_scalar_f(const void* p) {
    int iv = *(const int*)p;
    if (iv >= -1000000 && iv <= 1000000) return (float)iv;
    return __int_as_float(iv);
}
__device__ __forceinline__ int clampi(int v, int lo, int hi) {
    return v < lo ? lo : (v > hi ? hi : v);
}

__device__ __forceinline__ void finalize_write(
    float b0, float b1, float b2, float b3, float b4,
    int i0, int i1, int i2, int i3, int i4,
    const float* __restrict__ FL, float* __restrict__ out,
    size_t qb, int n, int N, int M)
{
    float d0 = sqrtf(fmaxf(b0, 1e-12f));
    float d1 = sqrtf(fmaxf(b1, 1e-12f));
    float d2 = sqrtf(fmaxf(b2, 1e-12f));
    float d3 = sqrtf(fmaxf(b3, 1e-12f));
    float d4 = sqrtf(fmaxf(b4, 1e-12f));
    float w0 = 1.0f;
    float w1 = __expf(d0 - d1);
    float w2 = __expf(d0 - d2);
    float w3 = __expf(d0 - d3);
    float w4 = __expf(d0 - d4);
    float inv = 1.0f / (w0 + w1 + w2 + w3 + w4);
    float fx = w0*FL[i0] + w1*FL[i1] + w2*FL[i2] + w3*FL[i3] + w4*FL[i4];
    float fy = w0*FL[M+i0] + w1*FL[M+i1] + w2*FL[M+i2] + w3*FL[M+i3] + w4*FL[M+i4];
    float fz = w0*FL[2*M+i0] + w1*FL[2*M+i1] + w2*FL[2*M+i2] + w3*FL[2*M+i3] + w4*FL[2*M+i4];
    out[qb + n]         = fx * inv;
    out[qb + N + n]     = fy * inv;
    out[qb + 2 * N + n] = fz * inv;
}

__global__ void __launch_bounds__(TPB) fused_kernel(
    const float* __restrict__ xyz, const float* __restrict__ sxyz,
    const float* __restrict__ sflow, const void* __restrict__ rf_ptr,
    float* __restrict__ out, int N, int M)
{
    const int gt   = blockIdx.x * blockDim.x + threadIdx.x;
    const int lane = threadIdx.x & 31;
    const int gw   = gt >> 5;                      // global warp id
    const int nthreads = gridDim.x * blockDim.x;
    const unsigned FULL = 0xFFFFFFFFu;

    const float inv_sigma = 1.0f / (rf_ptr ? decode_scalar_f(rf_ptr) : 1.0f);
    const float h    = (2.0f * DOMAIN) / (float)GRID;
    const float invh = 1.0f / h;

    int* cnt_flat = (int*)g_cnt;
    uint32_t* tbl_flat = (uint32_t*)g_tbl;

    // ---- P0: zero counts ----
    if (gt == 0) g_ovf_cnt = 0;
    for (int i = gt; i < BMAX * NCELL; i += nthreads) cnt_flat[i] = 0;
    grid_sync();

    // ---- P1: bin sparse points ----
    for (int gid = gt; gid < BMAX * M; gid += nthreads) {
        int b = gid / M, m = gid - b * M;
        const float* P = sxyz + (size_t)b * 3 * M;
        float x = P[m] * inv_sigma;
        float y = P[M + m] * inv_sigma;
        float z = P[2 * M + m] * inv_sigma;
        int cx = clampi((int)floorf((x + DOMAIN) * invh), 0, GRID - 1);
        int cy = clampi((int)floorf((y + DOMAIN) * invh), 0, GRID - 1);
        int cz = clampi((int)floorf((z + DOMAIN) * invh), 0, GRID - 1);
        int c = (cz * GRID + cy) * GRID + cx;
        g_ptcell[b][m] = c;
        atomicAdd(&g_cnt[b][c], 1);
    }
    grid_sync();

    // ---- P2a: chunk sums (warp per chunk) ----
    if (gw < NCHUNKT) {
        int base = gw * CHUNKC + lane * 4;
        int s = cnt_flat[base] + cnt_flat[base + 1]
              + cnt_flat[base + 2] + cnt_flat[base + 3];
#pragma unroll
        for (int off = 16; off; off >>= 1) s += __shfl_down_sync(FULL, s, off);
        if (lane == 0) g_chunksum[gw] = s;
    }
    grid_sync();

    // ---- P2b: per-batch exclusive chunk offsets (warp per batch) ----
    if (gw < BMAX) {
        int base = gw * CHPB + lane * 8;          // 256 chunks/batch, 8/lane
        int v[8];
        int sl = 0;
#pragma unroll
        for (int i = 0; i < 8; i++) { v[i] = g_chunksum[base + i]; sl += v[i]; }
        int sc = sl;
#pragma unroll
        for (int off = 1; off < 32; off <<= 1) {
            int y = __shfl_up_sync(FULL, sc, off);
            if (lane >= off) sc += y;
        }
        int run = sc - sl;                        // exclusive
#pragma unroll
        for (int i = 0; i < 8; i++) { g_chunkoff[base + i] = run; run += v[i]; }
    }
    grid_sync();

    // ---- P2c: emit CSR table + cursors (warp per chunk) ----
    if (gw < NCHUNKT) {
        int cbase = gw * CHUNKC + lane * 4;
        int c0 = cnt_flat[cbase],     c1 = cnt_flat[cbase + 1];
        int c2 = cnt_flat[cbase + 2], c3 = cnt_flat[cbase + 3];
        int tot = c0 + c1 + c2 + c3;
        int sc = tot;
#pragma unroll
        for (int off = 1; off < 32; off <<= 1) {
            int y = __shfl_up_sync(FULL, sc, off);
            if (lane >= off) sc += y;
        }
        int start = g_chunkoff[gw] + (sc - tot);
        tbl_flat[cbase]     = ((uint32_t)start << 16) | (uint32_t)c0;
        cnt_flat[cbase]     = start; start += c0;
        tbl_flat[cbase + 1] = ((uint32_t)start << 16) | (uint32_t)c1;
        cnt_flat[cbase + 1] = start; start += c1;
        tbl_flat[cbase + 2] = ((uint32_t)start << 16) | (uint32_t)c2;
        cnt_flat[cbase + 2] = start; start += c2;
        tbl_flat[cbase + 3] = ((uint32_t)start << 16) | (uint32_t)c3;
        cnt_flat[cbase + 3] = start;
    }
    grid_sync();

    // ---- P3: scatter points ----
    for (int gid = gt; gid < BMAX * M; gid += nthreads) {
        int b = gid / M, m = gid - b * M;
        const float* P = sxyz + (size_t)b * 3 * M;
        float x = P[m] * inv_sigma;
        float y = P[M + m] * inv_sigma;
        float z = P[2 * M + m] * inv_sigma;
        float p2 = fmaf(x, x, fmaf(y, y, z * z));
        int pos = atomicAdd(&g_cnt[b][g_ptcell[b][m]], 1);
        g_pts[b][pos] = make_float4(x, y, z, p2);
        g_pidx[b][pos] = m;
    }
    grid_sync();

    // ---- P4: pass 1 — capped ring search (thread per query) ----
    const float MARGIN = 1.0f + 1e-5f;
    for (int gid = gt; gid < BMAX * N; gid += nthreads) {
        int b = gid / N, n = gid - b * N;
        size_t qb = (size_t)b * 3 * N;
        float qx = xyz[qb + n] * inv_sigma;
        float qy = xyz[qb + N + n] * inv_sigma;
        float qz = xyz[qb + 2 * N + n] * inv_sigma;

        if (fabsf(qx) >= DOMAIN || fabsf(qy) >= DOMAIN || fabsf(qz) >= DOMAIN) {
            int slot = atomicAdd(&g_ovf_cnt, 1);
            g_ovf[slot] = (b << 20) | n;
            continue;
        }

        float q2 = fmaf(qx, qx, fmaf(qy, qy, qz * qz));
        float m2x = -2.0f * qx, m2y = -2.0f * qy, m2z = -2.0f * qz;
        int cx = clampi((int)floorf((qx + DOMAIN) * invh), 0, GRID - 1);
        int cy = clampi((int)floorf((qy + DOMAIN) * invh), 0, GRID - 1);
        int cz = clampi((int)floorf((qz + DOMAIN) * invh), 0, GRID - 1);

        float b0 = F_INF, b1 = F_INF, b2 = F_INF, b3 = F_INF, b4 = F_INF;
        int   i0 = 0, i1 = 0, i2 = 0, i3 = 0, i4 = 0;
        bool done = false;

        for (int r = 0; r <= RMAX; ++r) {
            if (r >= 2) {
                float bound = (float)(r - 1) * h;
                if (b4 * MARGIN <= bound * bound) { done = true; break; }
            }
            int zlo = cz - r < 0 ? 0 : cz - r, zhi = cz + r > GRID - 1 ? GRID - 1 : cz + r;
            int ylo = cy - r < 0 ? 0 : cy - r, yhi = cy + r > GRID - 1 ? GRID - 1 : cy + r;
            int xlo = cx - r < 0 ? 0 : cx - r, xhi = cx + r > GRID - 1 ? GRID - 1 : cx + r;
            for (int z = zlo; z <= zhi; ++z) {
                int az = z - cz; az = az < 0 ? -az : az;
                for (int y = ylo; y <= yhi; ++y) {
                    int ay = y - cy; ay = ay < 0 ? -ay : ay;
                    int am = az > ay ? az : ay;
                    for (int x = xlo; x <= xhi; ++x) {
                        int ax = x - cx; ax = ax < 0 ? -ax : ax;
                        int ch = am > ax ? am : ax;
                        if (ch != r) continue;

                        float lox = (x == 0)        ? -1e30f : fmaf((float)x, h, -DOMAIN);
                        float hix = (x == GRID - 1) ?  1e30f : fmaf((float)(x + 1), h, -DOMAIN);
                        float loy = (y == 0)        ? -1e30f : fmaf((float)y, h, -DOMAIN);
                        float hiy = (y == GRID - 1) ?  1e30f : fmaf((float)(y + 1), h, -DOMAIN);
                        float loz = (z == 0)        ? -1e30f : fmaf((float)z, h, -DOMAIN);
                        float hiz = (z == GRID - 1) ?  1e30f : fmaf((float)(z + 1), h, -DOMAIN);
                        float dx = fmaxf(lox - qx, fmaxf(qx - hix, 0.0f));
                        float dy = fmaxf(loy - qy, fmaxf(qy - hiy, 0.0f));
                        float dz = fmaxf(loz - qz, fmaxf(qz - hiz, 0.0f));
                        float md2 = fmaf(dx, dx, fmaf(dy, dy, dz * dz));
                        if (md2 > b4 * MARGIN) continue;

                        uint32_t tbl = g_tbl[b][(z * GRID + y) * GRID + x];
                        int cnt = (int)(tbl & 0xFFFFu);
                        int st  = (int)(tbl >> 16);
                        for (int t = 0; t < cnt; ++t) {
                            float4 p = g_pts[b][st + t];
                            float s = fmaf(m2x, p.x,
                                      fmaf(m2y, p.y,
                                      fmaf(m2z, p.z, q2 + p.w)));
                            if (s < b4) {
                                int j = g_pidx[b][st + t];
                                bool c3 = s < b3, c2 = s < b2, c1 = s < b1, c0 = s < b0;
                                b4 = c3 ? b3 : s;               i4 = c3 ? i3 : j;
                                b3 = c3 ? (c2 ? b2 : s) : b3;   i3 = c3 ? (c2 ? i2 : j) : i3;
                                b2 = c2 ? (c1 ? b1 : s) : b2;   i2 = c2 ? (c1 ? i1 : j) : i2;
                                b1 = c1 ? (c0 ? b0 : s) : b1;   i1 = c1 ? (c0 ? i0 : j) : i1;
                                b0 = c0 ? s : b0;               i0 = c0 ? j : i0;
                            }
                        }
                    }
                }
            }
        }
        if (!done) {
            float bound = (float)RMAX * h;
            done = (b4 * MARGIN <= bound * bound);
        }
        if (!done) {
            int slot = atomicAdd(&g_ovf_cnt, 1);
            g_ovf[slot] = (b << 20) | n;
            continue;
        }
        finalize_write(b0, b1, b2, b3, b4, i0, i1, i2, i3, i4,
                       sflow + (size_t)b * 3 * M, out, qb, n, N, M);
    }
    grid_sync();

    // ---- P5: pass 2 — warp-per-query exact brute force ----
    {
        const int nwarps = nthreads >> 5;
        const int total = g_ovf_cnt;
        for (int q = gw; q < total; q += nwarps) {
            int packed = g_ovf[q];
            int b = packed >> 20;
            int n = packed & 0xFFFFF;
            size_t qb = (size_t)b * 3 * N;
            float qx = xyz[qb + n] * inv_sigma;
            float qy = xyz[qb + N + n] * inv_sigma;
            float qz = xyz[qb + 2 * N + n] * inv_sigma;
            float q2 = fmaf(qx, qx, fmaf(qy, qy, qz * qz));
            float m2x = -2.0f * qx, m2y = -2.0f * qy, m2z = -2.0f * qz;

            float b0 = F_INF, b1 = F_INF, b2 = F_INF, b3 = F_INF, b4 = F_INF;
            int   i0 = 0, i1 = 0, i2 = 0, i3 = 0, i4 = 0;
            for (int t = lane; t < M; t += 32) {
                float4 p = g_pts[b][t];
                float s = fmaf(m2x, p.x, fmaf(m2y, p.y, fmaf(m2z, p.z, q2 + p.w)));
                if (s < b4) {
                    int j = g_pidx[b][t];
                    bool c3 = s < b3, c2 = s < b2, c1 = s < b1, c0 = s < b0;
                    b4 = c3 ? b3 : s;               i4 = c3 ? i3 : j;
                    b3 = c3 ? (c2 ? b2 : s) : b3;   i3 = c3 ? (c2 ? i2 : j) : i3;
                    b2 = c2 ? (c1 ? b1 : s) : b2;   i2 = c2 ? (c1 ? i1 : j) : i2;
                    b1 = c1 ? (c0 ? b0 : s) : b1;   i1 = c1 ? (c0 ? i0 : j) : i1;
                    b0 = c0 ? s : b0;               i0 = c0 ? j : i0;
                }
            }

            float rs[5]; int ri[5];
#pragma unroll
            for (int k = 0; k < 5; ++k) {
                float v = b0; int l = lane;
#pragma unroll
                for (int off = 16; off; off >>= 1) {
                    float ov = __shfl_down_sync(FULL, v, off);
                    int   ol = __shfl_down_sync(FULL, l, off);
                    if (ov < v) { v = ov; l = ol; }
                }
                v = __shfl_sync(FULL, v, 0);
                l = __shfl_sync(FULL, l, 0);
                int gidx = __shfl_sync(FULL, i0, l);
                rs[k] = v; ri[k] = gidx;
                if (lane == l) {
                    b0 = b1; i0 = i1; b1 = b2; i1 = i2;
                    b2 = b3; i2 = i3; b3 = b4; i3 = i4; b4 = F_INF;
                }
            }

            if (lane == 0) {
                finalize_write(rs[0], rs[1], rs[2], rs[3], rs[4],
                               ri[0], ri[1], ri[2], ri[3], ri[4],
                               sflow + (size_t)b * 3 * M, out, qb, n, N, M);
            }
        }
    }
}

// ---------------- launch ----------------
extern "C" void kernel_launch(void* const* d_in, const int* in_sizes, int n_in,
                              void* d_out, int out_size) {
    const float* xyz   = (const float*)d_in[0];
    const float* sxyz  = (const float*)d_in[1];
    const float* sflow = (const float*)d_in[2];
    const void*  rf    = (n_in > 3) ? d_in[3] : nullptr;
    float* out = (float*)d_out;

    const int B = BMAX;
    const int N = in_sizes[0] / (3 * B);   // 16384
    int M = in_sizes[1] / (3 * B);         // 4096
    if (M > MMAX) M = MMAX;

    fused_kernel<<<NCTA, TPB>>>(xyz, sxyz, sflow, rf, out, N, M);
}